// round 17
// baseline (speedup 1.0000x reference)
#include <cuda_runtime.h>
#include <math.h>

#define N_NODES 8192
#define F_IN    256
#define F_OUT   64

__device__ float g_fts[(size_t)N_NODES * F_OUT];
__device__ float g_f1[N_NODES];
__device__ float g_f2[N_NODES];

// ---------------------------------------------------------------------------
// Kernel 1: fts = x @ W  (+ fused f1/f2 projections)
// Crossbar-efficient tiling: each thread computes 4 nodes x 4 feats, so each
// pair of LDS.128 (xs node-quad + ws feat-quad) feeds 16 FFMAs. Previous
// tilings (1 node/thread) were smem-crossbar bound (~6 crossbar cyc / 4 FMA
// -> ~20us); this cuts crossbar ~6x below the ~8us FFMA-issue floor.
// GN=64 nodes/CTA -> 128 CTAs. KB=32, register double-buffered loads.
// ---------------------------------------------------------------------------
#define GN 64
#define KB 32
#define NPH (F_IN / KB)   // 8 phases

__global__ void __launch_bounds__(256) gemm_kernel(const float* __restrict__ x,
                                                   const float* __restrict__ W,
                                                   const float* __restrict__ a1,
                                                   const float* __restrict__ b1,
                                                   const float* __restrict__ a2,
                                                   const float* __restrict__ b2) {
    __shared__ float xs[KB][GN + 4];     // xs[k][n], row stride 272B (16B-mult)
    __shared__ float ws[KB][F_OUT];      // ws[k][f]
    __shared__ float r1[16][GN + 1];     // per-tf partial dots with a1
    __shared__ float r2[16][GN + 1];     // per-tf partial dots with a2

    const int tid = threadIdx.x;
    const int n0  = blockIdx.x * GN;
    const int tn  = tid & 15;            // node quad (4 nodes)
    const int tf  = tid >> 4;            // feature quad (0..15)

    float acc[4][4] = {};

    // ---- preload phase 0 into registers (2 x-quads + 2 w-quads / thread) ----
    float4 xv[2], wv[2];
    #pragma unroll
    for (int r = 0; r < 2; r++) {
        int idx = tid + r * 256;                 // 0..511
        xv[r] = *reinterpret_cast<const float4*>(
            &x[(size_t)(n0 + (idx >> 3)) * F_IN + (idx & 7) * 4]);
        wv[r] = *reinterpret_cast<const float4*>(
            &W[(size_t)(idx >> 4) * F_OUT + (idx & 15) * 4]);
    }

    #pragma unroll
    for (int p = 0; p < NPH; p++) {
        // stage current registers into smem
        #pragma unroll
        for (int r = 0; r < 2; r++) {
            int idx = tid + r * 256;
            int n   = idx >> 3;                  // 0..63
            int kq  = idx & 7;                   // 0..7
            xs[kq * 4 + 0][n] = xv[r].x;
            xs[kq * 4 + 1][n] = xv[r].y;
            xs[kq * 4 + 2][n] = xv[r].z;
            xs[kq * 4 + 3][n] = xv[r].w;
            *reinterpret_cast<float4*>(&ws[idx >> 4][(idx & 15) * 4]) = wv[r];
        }
        __syncthreads();

        // prefetch next phase (overlaps with compute below)
        if (p + 1 < NPH) {
            int kb = (p + 1) * KB;
            #pragma unroll
            for (int r = 0; r < 2; r++) {
                int idx = tid + r * 256;
                xv[r] = *reinterpret_cast<const float4*>(
                    &x[(size_t)(n0 + (idx >> 3)) * F_IN + kb + (idx & 7) * 4]);
                wv[r] = *reinterpret_cast<const float4*>(
                    &W[(size_t)(kb + (idx >> 4)) * F_OUT + (idx & 15) * 4]);
            }
        }

        // compute: per k, 2 LDS.128 -> 16 FFMA
        #pragma unroll
        for (int k = 0; k < KB; k++) {
            float4 xq = *reinterpret_cast<const float4*>(&xs[k][tn * 4]);
            float4 wq = *reinterpret_cast<const float4*>(&ws[k][tf * 4]);
            float xr[4] = {xq.x, xq.y, xq.z, xq.w};
            float wr[4] = {wq.x, wq.y, wq.z, wq.w};
            #pragma unroll
            for (int i = 0; i < 4; i++)
                #pragma unroll
                for (int j = 0; j < 4; j++)
                    acc[i][j] += xr[i] * wr[j];
        }
        __syncthreads();
    }

    // store fts + fused projection partials (4 nodes per thread)
    float4 a1v = *reinterpret_cast<const float4*>(&a1[tf * 4]);
    float4 a2v = *reinterpret_cast<const float4*>(&a2[tf * 4]);
    #pragma unroll
    for (int i = 0; i < 4; i++) {
        int n = n0 + tn * 4 + i;
        *reinterpret_cast<float4*>(&g_fts[(size_t)n * F_OUT + tf * 4]) =
            make_float4(acc[i][0], acc[i][1], acc[i][2], acc[i][3]);
        r1[tf][tn * 4 + i] = acc[i][0] * a1v.x + acc[i][1] * a1v.y
                           + acc[i][2] * a1v.z + acc[i][3] * a1v.w;
        r2[tf][tn * 4 + i] = acc[i][0] * a2v.x + acc[i][1] * a2v.y
                           + acc[i][2] * a2v.z + acc[i][3] * a2v.w;
    }
    __syncthreads();

    if (tid < GN) {
        float s = 0.f;
        #pragma unroll
        for (int t = 0; t < 16; t++) s += r1[t][tid];
        g_f1[n0 + tid] = s + b1[0];
    } else if (tid < 2 * GN) {
        int nn = tid - GN;
        float s = 0.f;
        #pragma unroll
        for (int t = 0; t < 16; t++) s += r2[t][nn];
        g_f2[n0 + nn] = s + b2[0];
    }
}

// ---------------------------------------------------------------------------
// Kernel 2: persistent attention CTAs with next-row prefetch.
// Grid = 1184 CTAs, each processes rows row, row+1184, ... After the zero-
// scan consumes a[8], the NEXT row's 8 __ldcs loads are issued before the
// current row's (serial, barrier-heavy) epilogue runs — keeping DRAM busy
// through the ~38% of time the R14 profile showed it idle.
// ---------------------------------------------------------------------------
#define GRID_ATTN 1184
#define CAP 1024

__global__ void __launch_bounds__(256) attn_kernel(const float* __restrict__ adj,
                                                   const float* __restrict__ bias,
                                                   float* __restrict__ out) {
    __shared__ float          s_sc[CAP];
    __shared__ unsigned short s_j[CAP];
    __shared__ float          red[8];
    __shared__ float          part[4][F_OUT];
    __shared__ int            s_cnt;
    __shared__ float          s_stat[2];   // [0]=max, [1]=sum

    const int tid = threadIdx.x;
    const int f   = tid & 63;
    const int c   = tid >> 6;

    int row = blockIdx.x;
    float4 a[8];
    if (row < N_NODES) {
        const float4* arow4 = reinterpret_cast<const float4*>(adj + (size_t)row * N_NODES);
        #pragma unroll
        for (int k = 0; k < 8; k++)
            a[k] = __ldcs(&arow4[tid + k * 256]);
    }

    while (row < N_NODES) {
        const float f1i = g_f1[row];
        if (tid == 0) s_cnt = 0;
        __syncthreads();

        // ---- zero-scan + index compaction (consumes a[]) ----
        #pragma unroll
        for (int k = 0; k < 8; k++) {
            float m = fminf(fminf(fabsf(a[k].x), fabsf(a[k].y)),
                            fminf(fabsf(a[k].z), fabsf(a[k].w)));
            if (m == 0.0f) {
                int jb = (tid + k * 256) * 4;
                if (a[k].x == 0.0f) { int p = atomicAdd(&s_cnt, 1); if (p < CAP) s_j[p] = (unsigned short)(jb + 0); }
                if (a[k].y == 0.0f) { int p = atomicAdd(&s_cnt, 1); if (p < CAP) s_j[p] = (unsigned short)(jb + 1); }
                if (a[k].z == 0.0f) { int p = atomicAdd(&s_cnt, 1); if (p < CAP) s_j[p] = (unsigned short)(jb + 2); }
                if (a[k].w == 0.0f) { int p = atomicAdd(&s_cnt, 1); if (p < CAP) s_j[p] = (unsigned short)(jb + 3); }
            }
        }
        __syncthreads();
        const int M       = s_cnt;
        const int nextrow = row + GRID_ATTN;

        // ---- prefetch next row's adj (overlaps the epilogue below) ----
        if (nextrow < N_NODES) {
            const float4* nrow4 = reinterpret_cast<const float4*>(adj + (size_t)nextrow * N_NODES);
            #pragma unroll
            for (int k = 0; k < 8; k++)
                a[k] = __ldcs(&nrow4[tid + k * 256]);
        }

        if (M > 0 && M <= CAP) {
            // ---- scores for compacted indices + max ----
            float lm = -3.4e38f;
            for (int l = tid; l < M; l += 256) {
                int   j = s_j[l];
                float t = f1i + g_f2[j];
                t = (t > 0.f ? t : 0.2f * t);
                s_sc[l] = t;
                lm = fmaxf(lm, t);
            }
            #pragma unroll
            for (int o = 16; o > 0; o >>= 1)
                lm = fmaxf(lm, __shfl_xor_sync(0xffffffffu, lm, o));
            if ((tid & 31) == 0) red[tid >> 5] = lm;
            __syncthreads();
            if (tid == 0) {
                float m = red[0];
                #pragma unroll
                for (int w = 1; w < 8; w++) m = fmaxf(m, red[w]);
                s_stat[0] = m;
            }
            __syncthreads();
            const float bmax = s_stat[0];

            // ---- exp + sum ----
            float lsum = 0.f;
            for (int l = tid; l < M; l += 256) {
                float w = expf(s_sc[l] - bmax);
                s_sc[l] = w;
                lsum += w;
            }
            #pragma unroll
            for (int o = 16; o > 0; o >>= 1)
                lsum += __shfl_xor_sync(0xffffffffu, lsum, o);
            if ((tid & 31) == 0) red[tid >> 5] = lsum;
            __syncthreads();
            if (tid == 0) {
                float s = red[0];
                #pragma unroll
                for (int w = 1; w < 8; w++) s += red[w];
                s_stat[1] = s;
            }
            __syncthreads();

            // ---- weighted sum of fts rows ----
            float acc = 0.f;
            for (int l = c; l < M; l += 4)
                acc += s_sc[l] * g_fts[(size_t)s_j[l] * F_OUT + f];
            part[c][f] = acc;
            __syncthreads();

            if (tid < F_OUT) {
                float v = (part[0][f] + part[1][f] + part[2][f] + part[3][f])
                          / s_stat[1] + bias[f];
                out[(size_t)row * F_OUT + f] = (v > 0.f) ? v : expm1f(v);
            }
        } else {
            // ---- exact dense fallback (degenerate rows; effectively never) ----
            const float* arow = adj + (size_t)row * N_NODES;
            float lm = -3.4e38f;
            for (int j = tid; j < N_NODES; j += 256) {
                float t = f1i + g_f2[j];
                t = (t > 0.f ? t : 0.2f * t) + arow[j];
                lm = fmaxf(lm, t);
            }
            #pragma unroll
            for (int o = 16; o > 0; o >>= 1)
                lm = fmaxf(lm, __shfl_xor_sync(0xffffffffu, lm, o));
            if ((tid & 31) == 0) red[tid >> 5] = lm;
            __syncthreads();
            if (tid == 0) {
                float m = red[0];
                #pragma unroll
                for (int w = 1; w < 8; w++) m = fmaxf(m, red[w]);
                s_stat[0] = m;
            }
            __syncthreads();
            const float bmax = s_stat[0];

            float acc = 0.f, wsum = 0.f;
            for (int j = c; j < N_NODES; j += 4) {
                float t = f1i + g_f2[j];
                t = (t > 0.f ? t : 0.2f * t) + arow[j];
                float w = expf(t - bmax);
                wsum += w;
                acc  += w * g_fts[(size_t)j * F_OUT + f];
            }
            part[c][f] = acc;
            if (f == 0) red[c] = wsum;
            __syncthreads();
            if (tid < F_OUT) {
                float tot = red[0] + red[1] + red[2] + red[3];
                float v = (part[0][f] + part[1][f] + part[2][f] + part[3][f])
                          / tot + bias[f];
                out[(size_t)row * F_OUT + f] = (v > 0.f) ? v : expm1f(v);
            }
        }

        row = nextrow;
    }
}

// ---------------------------------------------------------------------------
// Launch
// ---------------------------------------------------------------------------
extern "C" void kernel_launch(void* const* d_in, const int* in_sizes, int n_in,
                              void* d_out, int out_size) {
    const float* x    = (const float*)d_in[0];
    const float* adj  = (const float*)d_in[1];
    const float* W    = (const float*)d_in[2];
    const float* a1   = (const float*)d_in[3];
    const float* b1   = (const float*)d_in[4];
    const float* a2   = (const float*)d_in[5];
    const float* b2   = (const float*)d_in[6];
    const float* bias = (const float*)d_in[7];
    float* out = (float*)d_out;

    gemm_kernel<<<N_NODES / GN, 256>>>(x, W, a1, b1, a2, b2);
    attn_kernel<<<GRID_ATTN, 256>>>(adj, bias, out);
}